// round 6
// baseline (speedup 1.0000x reference)
#include <cuda_runtime.h>
#include <math.h>

#define DD 128
static constexpr int MAXG = 5120;
static constexpr int MAXE = 262144;
static constexpr int HR   = 8;       // h1 replication (atomic decontention)
static constexpr int W1SM = DD * DD * 4;  // 64KB W1 slice per block

__device__ __align__(16) float g_xl [MAXG * DD];
__device__ __align__(16) float g_xr [MAXG * DD];
__device__ int   g_src[MAXE];
__device__ int   g_dst[MAXE];
__device__ int   g_es [MAXE];
__device__ int   g_off[MAXG + 1];
__device__ int   g_cur[MAXG];
__device__ int   g_deg[MAXG];
__device__ float g_h1p[HR][DD];
__device__ int   g_flag = 0;   // never reset: input dtype fixed across replays.

// ---------------------------------------------------------------------------
// K1: blocks [0,zB): zero deg + h1 replicas. Block zB: dtype detect (256
// samples): int64 ids (<G) have zero odd words; int32 odd words are random.
// ---------------------------------------------------------------------------
__global__ void ksetup(const int* __restrict__ w, int E, int G, int zB) {
    if ((int)blockIdx.x < zB) {
        int i = blockIdx.x * 256 + threadIdx.x;
        if (i < G) g_deg[i] = 0;
        if (i < HR * DD) ((float*)g_h1p)[i] = 0.f;
        return;
    }
    int i = threadIdx.x;
    int v = 0;
    if (i < E) v = w[2 * i + 1];
    #pragma unroll
    for (int o = 16; o; o >>= 1) v |= __shfl_xor_sync(0xffffffffu, v, o);
    if ((threadIdx.x & 31) == 0 && v) atomicOr(&g_flag, 1);
}

// ---------------------------------------------------------------------------
// K2: edge convert + degree histogram (2 edges/thread for atomic MLP)
// ---------------------------------------------------------------------------
__global__ void kconv(const void* __restrict__ eidx, int E) {
    int i0 = (blockIdx.x * 256 + threadIdx.x) * 2;
    #pragma unroll
    for (int k = 0; k < 2; k++) {
        int i = i0 + k;
        if (i >= E) return;
        int s, d;
        if (g_flag == 0) {
            const long long* p = (const long long*)eidx;
            s = (int)p[i]; d = (int)p[(size_t)E + i];
        } else {
            const int* p = (const int*)eidx;
            s = p[i]; d = p[E + i];
        }
        g_src[i] = s;
        g_dst[i] = d;
        atomicAdd(&g_deg[d], 1);
    }
}

// ---------------------------------------------------------------------------
// K3: single-block scan, 5 elems/thread + warp-shuffle block scan
// ---------------------------------------------------------------------------
__global__ void kscan(int G) {
    __shared__ int wsum[32];
    int tid = threadIdx.x, lane = tid & 31, wid = tid >> 5;
    int base = tid * 5;
    int v[5]; int s = 0;
    #pragma unroll
    for (int k = 0; k < 5; k++) {
        int i = base + k;
        v[k] = (i < G) ? g_deg[i] : 0;
        s += v[k];
    }
    int xinc = s;
    #pragma unroll
    for (int o = 1; o < 32; o <<= 1) {
        int t = __shfl_up_sync(0xffffffffu, xinc, o);
        if (lane >= o) xinc += t;
    }
    if (lane == 31) wsum[wid] = xinc;
    __syncthreads();
    if (wid == 0) {
        int y = wsum[lane];
        #pragma unroll
        for (int o = 1; o < 32; o <<= 1) {
            int t = __shfl_up_sync(0xffffffffu, y, o);
            if (lane >= o) y += t;
        }
        wsum[lane] = y;
    }
    __syncthreads();
    int run = xinc - s + (wid ? wsum[wid - 1] : 0);
    #pragma unroll
    for (int k = 0; k < 5; k++) {
        int i = base + k;
        if (i < G) {
            g_cur[i] = run;
            run += v[k];
            g_off[i + 1] = run;
        }
    }
    if (tid == 0) g_off[0] = 0;
}

// ---------------------------------------------------------------------------
// K4: scatter edges into CSR buckets (4 edges/thread for atomic MLP)
// ---------------------------------------------------------------------------
__global__ void kscatter(int E) {
    int i0 = (blockIdx.x * blockDim.x + threadIdx.x) * 4;
    #pragma unroll
    for (int k = 0; k < 4; k++) {
        int i = i0 + k;
        if (i >= E) return;
        int d   = g_dst[i];
        int pos = atomicAdd(&g_cur[d], 1);
        g_es[pos] = g_src[i];
    }
}

// ---------------------------------------------------------------------------
// K5: fused h + xl/xr. 8 genes / 256-thread block; h lives only in smem.
// ---------------------------------------------------------------------------
__global__ void khx(const float* __restrict__ x, const float* __restrict__ Win,
                    const float* __restrict__ bin,
                    const float* __restrict__ Wl, const float* __restrict__ bl,
                    const float* __restrict__ Wr, const float* __restrict__ br,
                    int IN, int G) {
    __shared__ float sh[8][DD];
    int tid = threadIdx.x, lane = tid & 31, wid = tid >> 5;
    int g0 = blockIdx.x * 8;
    int g  = g0 + wid;

    float4 acc = make_float4(0.f, 0.f, 0.f, 0.f);
    if (g < G) {
        const float4* w4 = (const float4*)(Win + (size_t)g * IN * DD);
        const float*  xg = x + (size_t)g * IN;
        #pragma unroll 8
        for (int i = 0; i < IN; i++) {
            float  xi = xg[i];
            float4 w  = w4[(size_t)i * 32 + lane];
            acc.x = fmaf(xi, w.x, acc.x);
            acc.y = fmaf(xi, w.y, acc.y);
            acc.z = fmaf(xi, w.z, acc.z);
            acc.w = fmaf(xi, w.w, acc.w);
        }
        float4 bv = ((const float4*)(bin + (size_t)g * DD))[lane];
        acc.x = fmaxf(acc.x + bv.x, 0.f);
        acc.y = fmaxf(acc.y + bv.y, 0.f);
        acc.z = fmaxf(acc.z + bv.z, 0.f);
        acc.w = fmaxf(acc.w + bv.w, 0.f);
    }
    ((float4*)sh[wid])[lane] = acc;
    __syncthreads();

    int d    = tid & 127;
    int half = tid >> 7;
    const float* W   = half ? Wr : Wl;
    const float* bb  = half ? br : bl;
    float*       out = half ? g_xr : g_xl;
    float bd = bb[d];
    float a[8];
    #pragma unroll
    for (int r = 0; r < 8; r++) a[r] = bd;
    #pragma unroll 4
    for (int k = 0; k < DD; k++) {
        float w = W[k * DD + d];
        #pragma unroll
        for (int r = 0; r < 8; r++) a[r] = fmaf(sh[r][k], w, a[r]);
    }
    #pragma unroll
    for (int r = 0; r < 8; r++) {
        int gg = g0 + r;
        if (gg < G) out[(size_t)gg * DD + d] = a[r];
    }
}

// ---------------------------------------------------------------------------
// online-softmax single-edge update (one accumulator set)
// ---------------------------------------------------------------------------
__device__ __forceinline__ void gat_step(int src, float4 xr4, float4 att4,
                                         const float4* xlv, int lane,
                                         float& m, float& z, float4& acc) {
    float4 xl4 = xlv[(size_t)src * (DD / 4) + lane];
    float tx = xl4.x + xr4.x, ty = xl4.y + xr4.y;
    float tz = xl4.z + xr4.z, tw = xl4.w + xr4.w;
    tx = tx >= 0.f ? tx : 0.2f * tx;
    ty = ty >= 0.f ? ty : 0.2f * ty;
    tz = tz >= 0.f ? tz : 0.2f * tz;
    tw = tw >= 0.f ? tw : 0.2f * tw;
    float p = att4.x * tx + att4.y * ty + att4.z * tz + att4.w * tw;
    #pragma unroll
    for (int o = 16; o; o >>= 1) p += __shfl_xor_sync(0xffffffffu, p, o);
    float mn = fmaxf(m, p);
    float sc = __expf(m - mn);
    float w  = __expf(p - mn);
    z     = z * sc + w;
    acc.x = acc.x * sc + w * xl4.x;
    acc.y = acc.y * sc + w * xl4.y;
    acc.z = acc.z * sc + w * xl4.z;
    acc.w = acc.w * sc + w * xl4.w;
    m = mn;
}

// ---------------------------------------------------------------------------
// K6: FUSED GATv2 + MLP1 slice, with cp.async W1 prefetch overlapping the
// gather. 256 threads / block, one destination node per block.
//   t=0 : issue all 64KB of this block's W1 slice as cp.async (16B each)
//   then: 8-warp gather, 2 independent online-softmax sets per warp (ILP)
//   then: cp.async.wait_all; FMA h1 partials from SMEM; reduce; atomics.
// ---------------------------------------------------------------------------
__global__ void kgm(const float* __restrict__ att, const float* __restrict__ bias,
                    const float* __restrict__ W1) {
    extern __shared__ float4 sW1[];                 // 4096 float4 = 64KB
    int n = blockIdx.x;
    int tid = threadIdx.x, lane = tid & 31, wid = tid >> 5;

    // ---- prefetch W1 slice (rows n*128..n*128+127) into smem ----
    {
        const float4* gsrc = (const float4*)(W1 + (size_t)n * DD * DD) + tid;
        unsigned saddr = (unsigned)__cvta_generic_to_shared(sW1 + tid);
        #pragma unroll
        for (int k = 0; k < 16; k++) {
            asm volatile("cp.async.cg.shared.global [%0], [%1], 16;\n"
                         :: "r"(saddr + k * 256 * 16), "l"(gsrc + k * 256));
        }
        asm volatile("cp.async.commit_group;\n");
    }

    // ---- gather phase (8 warps, 2-way ILP online softmax) ----
    const float4* xlv = (const float4*)g_xl;
    float4 att4 = ((const float4*)att)[lane];
    float4 xr4  = ((const float4*)(g_xr + (size_t)n * DD))[lane];

    int beg = g_off[n], end = g_off[n + 1];
    float  m0 = -INFINITY, z0 = 0.f, m1 = -INFINITY, z1 = 0.f;
    float4 a0 = make_float4(0.f, 0.f, 0.f, 0.f);
    float4 a1 = make_float4(0.f, 0.f, 0.f, 0.f);

    if (wid == 0) gat_step(n, xr4, att4, xlv, lane, m0, z0, a0);  // self loop
    for (int i = beg + wid; i < end; i += 16) {
        int s0 = g_es[i];
        int s1 = (i + 8 < end) ? g_es[i + 8] : -1;
        gat_step(s0, xr4, att4, xlv, lane, m0, z0, a0);
        if (s1 >= 0) gat_step(s1, xr4, att4, xlv, lane, m1, z1, a1);
    }
    // merge set1 into set0 (m1 may be -inf -> s1 = 0)
    {
        float M = fmaxf(m0, m1);
        float s0 = __expf(m0 - M), s1 = __expf(m1 - M);
        z0   = z0 * s0 + z1 * s1;
        a0.x = a0.x * s0 + a1.x * s1;
        a0.y = a0.y * s0 + a1.y * s1;
        a0.z = a0.z * s0 + a1.z * s1;
        a0.w = a0.w * s0 + a1.w * s1;
        m0 = M;
    }

    __shared__ float sm[8], szz[8];
    __shared__ float sacc[8][DD];
    __shared__ float sgat[DD];
    if (lane == 0) { sm[wid] = m0; szz[wid] = z0; }
    sacc[wid][lane * 4 + 0] = a0.x;
    sacc[wid][lane * 4 + 1] = a0.y;
    sacc[wid][lane * 4 + 2] = a0.z;
    sacc[wid][lane * 4 + 3] = a0.w;
    __syncthreads();

    if (tid < DD) {
        int d = tid;
        float M = sm[0];
        #pragma unroll
        for (int w2 = 1; w2 < 8; w2++) M = fmaxf(M, sm[w2]);
        float Z = 0.f, A = 0.f;
        #pragma unroll
        for (int w2 = 0; w2 < 8; w2++) {
            float s = __expf(sm[w2] - M);
            Z += szz[w2] * s;
            A += sacc[w2][d] * s;
        }
        float o = A / Z + bias[d];
        sgat[d] = o >= 0.f ? o : 0.2f * o;
    }

    // ---- wait for W1, then FMA from smem ----
    asm volatile("cp.async.wait_group 0;\n");
    __syncthreads();

    float4 h = make_float4(0.f, 0.f, 0.f, 0.f);
    #pragma unroll
    for (int r = wid; r < DD; r += 8) {
        float  f = sgat[r];
        float4 w = sW1[r * 32 + lane];
        h.x = fmaf(f, w.x, h.x);
        h.y = fmaf(f, w.y, h.y);
        h.z = fmaf(f, w.z, h.z);
        h.w = fmaf(f, w.w, h.w);
    }
    __shared__ float4 sred[8][32];
    sred[wid][lane] = h;
    __syncthreads();
    if (wid == 0) {
        float4 a = sred[0][lane];
        #pragma unroll
        for (int w2 = 1; w2 < 8; w2++) {
            float4 b = sred[w2][lane];
            a.x += b.x; a.y += b.y; a.z += b.z; a.w += b.w;
        }
        float* dst = g_h1p[n & (HR - 1)];
        atomicAdd(&dst[4 * lane + 0], a.x);
        atomicAdd(&dst[4 * lane + 1], a.y);
        atomicAdd(&dst[4 * lane + 2], a.z);
        atomicAdd(&dst[4 * lane + 3], a.w);
    }
}

// ---------------------------------------------------------------------------
// K7: out = relu(sum_replicas h1 + b1) @ W2 + b2
// ---------------------------------------------------------------------------
__global__ void kout(const float* __restrict__ b1, const float* __restrict__ W2,
                     const float* __restrict__ b2, float* __restrict__ out) {
    int d = threadIdx.x;
    float v = b1[d];
    #pragma unroll
    for (int r = 0; r < HR; r++) v += g_h1p[r][d];
    v = fmaxf(v, 0.f);
    float p = v * W2[d];
    #pragma unroll
    for (int o = 16; o; o >>= 1) p += __shfl_xor_sync(0xffffffffu, p, o);
    __shared__ float sp[4];
    if ((d & 31) == 0) sp[d >> 5] = p;
    __syncthreads();
    if (d == 0) out[0] = sp[0] + sp[1] + sp[2] + sp[3] + b2[0];
}

// ---------------------------------------------------------------------------
extern "C" void kernel_launch(void* const* d_in, const int* in_sizes, int n_in,
                              void* d_out, int out_size) {
    const float* x    = (const float*)d_in[0];
    const void*  ei   = d_in[1];
    const float* Win  = (const float*)d_in[2];
    const float* bin  = (const float*)d_in[3];
    const float* Wl   = (const float*)d_in[4];
    const float* bl   = (const float*)d_in[5];
    const float* Wr   = (const float*)d_in[6];
    const float* br   = (const float*)d_in[7];
    const float* att  = (const float*)d_in[8];
    const float* bias = (const float*)d_in[9];
    const float* W1   = (const float*)d_in[10];
    const float* b1   = (const float*)d_in[11];
    const float* W2   = (const float*)d_in[12];
    const float* b2   = (const float*)d_in[13];

    int Dd = in_sizes[8];          // 128
    int G  = in_sizes[3] / Dd;     // 5000
    int IN = in_sizes[0] / G;      // 64
    int E  = in_sizes[1] / 2;      // 240000
    (void)n_in; (void)out_size; (void)Dd;

    static bool inited = false;
    static cudaStream_t sB;
    static cudaEvent_t evF, evE;
    if (!inited) {
        cudaStreamCreateWithFlags(&sB, cudaStreamNonBlocking);
        cudaEventCreateWithFlags(&evF, cudaEventDisableTiming);
        cudaEventCreateWithFlags(&evE, cudaEventDisableTiming);
        cudaFuncSetAttribute(kgm, cudaFuncAttributeMaxDynamicSharedMemorySize, W1SM);
        inited = true;
    }

    int zB = (G + 255) / 256;
    int eB2 = (E / 2 + 255) / 256;
    int eB4 = (E / 4 + 255) / 256;

    // fork edge pipeline onto sB, concurrent with the W_in stream (khx)
    cudaEventRecord(evF, 0);
    cudaStreamWaitEvent(sB, evF, 0);
    ksetup  <<<zB + 1, 256, 0, sB>>>((const int*)ei, E, G, zB);
    kconv   <<<eB2, 256, 0, sB>>>(ei, E);
    kscan   <<<1, 1024, 0, sB>>>(G);
    khx     <<<(G + 7) / 8, 256>>>(x, Win, bin, Wl, bl, Wr, br, IN, G);
    kscatter<<<eB4, 256, 0, sB>>>(E);
    cudaEventRecord(evE, sB);

    // join, then fused GAT + W1 stream, then output head
    cudaStreamWaitEvent(0, evE, 0);
    kgm <<<G, 256, W1SM>>>(att, bias, W1);
    kout<<<1, DD>>>(b1, W2, b2, (float*)d_out);
}

// round 7
// speedup vs baseline: 1.1053x; 1.1053x over previous
#include <cuda_runtime.h>
#include <math.h>

#define DD 128
static constexpr int MAXG = 5120;
static constexpr int MAXE = 262144;
static constexpr int HR   = 8;          // h1 replication (atomic decontention)
static constexpr int PREF_SLICES = 1536; // 1536 * 64KB = 96MB of W1 prefetched to L2

__device__ __align__(16) float g_xl [MAXG * DD];
__device__ __align__(16) float g_xr [MAXG * DD];
__device__ int   g_src[MAXE];
__device__ int   g_dst[MAXE];
__device__ int   g_es [MAXE];
__device__ int   g_off[MAXG + 1];
__device__ int   g_cur[MAXG];
__device__ int   g_deg[MAXG];
__device__ float g_h1p[HR][DD];
__device__ float g_sink;
__device__ int   g_flag = 0;   // never reset: input dtype fixed across replays.

// ---------------------------------------------------------------------------
// K1: blocks [0,zB): zero deg + h1 replicas. Block zB: dtype detect (256
// samples): int64 ids (<G) have zero odd words; int32 odd words are random.
// ---------------------------------------------------------------------------
__global__ void ksetup(const int* __restrict__ w, int E, int G, int zB) {
    if ((int)blockIdx.x < zB) {
        int i = blockIdx.x * 256 + threadIdx.x;
        if (i < G) g_deg[i] = 0;
        if (i < HR * DD) ((float*)g_h1p)[i] = 0.f;
        return;
    }
    int i = threadIdx.x;
    int v = 0;
    if (i < E) v = w[2 * i + 1];
    #pragma unroll
    for (int o = 16; o; o >>= 1) v |= __shfl_xor_sync(0xffffffffu, v, o);
    if ((threadIdx.x & 31) == 0 && v) atomicOr(&g_flag, 1);
}

// ---------------------------------------------------------------------------
// K2: edge convert + degree histogram (2 edges/thread)
// ---------------------------------------------------------------------------
__global__ void kconv(const void* __restrict__ eidx, int E) {
    int i0 = (blockIdx.x * 256 + threadIdx.x) * 2;
    #pragma unroll
    for (int k = 0; k < 2; k++) {
        int i = i0 + k;
        if (i >= E) return;
        int s, d;
        if (g_flag == 0) {
            const long long* p = (const long long*)eidx;
            s = (int)p[i]; d = (int)p[(size_t)E + i];
        } else {
            const int* p = (const int*)eidx;
            s = p[i]; d = p[E + i];
        }
        g_src[i] = s;
        g_dst[i] = d;
        atomicAdd(&g_deg[d], 1);
    }
}

// ---------------------------------------------------------------------------
// K3: single-block scan, 5 elems/thread + warp-shuffle block scan
// ---------------------------------------------------------------------------
__global__ void kscan(int G) {
    __shared__ int wsum[32];
    int tid = threadIdx.x, lane = tid & 31, wid = tid >> 5;
    int base = tid * 5;
    int v[5]; int s = 0;
    #pragma unroll
    for (int k = 0; k < 5; k++) {
        int i = base + k;
        v[k] = (i < G) ? g_deg[i] : 0;
        s += v[k];
    }
    int xinc = s;
    #pragma unroll
    for (int o = 1; o < 32; o <<= 1) {
        int t = __shfl_up_sync(0xffffffffu, xinc, o);
        if (lane >= o) xinc += t;
    }
    if (lane == 31) wsum[wid] = xinc;
    __syncthreads();
    if (wid == 0) {
        int y = wsum[lane];
        #pragma unroll
        for (int o = 1; o < 32; o <<= 1) {
            int t = __shfl_up_sync(0xffffffffu, y, o);
            if (lane >= o) y += t;
        }
        wsum[lane] = y;
    }
    __syncthreads();
    int run = xinc - s + (wid ? wsum[wid - 1] : 0);
    #pragma unroll
    for (int k = 0; k < 5; k++) {
        int i = base + k;
        if (i < G) {
            g_cur[i] = run;
            run += v[k];
            g_off[i + 1] = run;
        }
    }
    if (tid == 0) g_off[0] = 0;
}

// ---------------------------------------------------------------------------
// K4: scatter edges into CSR buckets (4 edges/thread)
// ---------------------------------------------------------------------------
__global__ void kscatter(int E) {
    int i0 = (blockIdx.x * blockDim.x + threadIdx.x) * 4;
    #pragma unroll
    for (int k = 0; k < 4; k++) {
        int i = i0 + k;
        if (i >= E) return;
        int d   = g_dst[i];
        int pos = atomicAdd(&g_cur[d], 1);
        g_es[pos] = g_src[i];
    }
}

// ---------------------------------------------------------------------------
// K5: fused h + xl/xr. 8 genes / 256-thread block; h lives only in smem.
// ---------------------------------------------------------------------------
__global__ void khx(const float* __restrict__ x, const float* __restrict__ Win,
                    const float* __restrict__ bin,
                    const float* __restrict__ Wl, const float* __restrict__ bl,
                    const float* __restrict__ Wr, const float* __restrict__ br,
                    int IN, int G) {
    __shared__ float sh[8][DD];
    int tid = threadIdx.x, lane = tid & 31, wid = tid >> 5;
    int g0 = blockIdx.x * 8;
    int g  = g0 + wid;

    float4 acc = make_float4(0.f, 0.f, 0.f, 0.f);
    if (g < G) {
        const float4* w4 = (const float4*)(Win + (size_t)g * IN * DD);
        const float*  xg = x + (size_t)g * IN;
        #pragma unroll 16
        for (int i = 0; i < IN; i++) {
            float  xi = xg[i];
            float4 w  = w4[(size_t)i * 32 + lane];
            acc.x = fmaf(xi, w.x, acc.x);
            acc.y = fmaf(xi, w.y, acc.y);
            acc.z = fmaf(xi, w.z, acc.z);
            acc.w = fmaf(xi, w.w, acc.w);
        }
        float4 bv = ((const float4*)(bin + (size_t)g * DD))[lane];
        acc.x = fmaxf(acc.x + bv.x, 0.f);
        acc.y = fmaxf(acc.y + bv.y, 0.f);
        acc.z = fmaxf(acc.z + bv.z, 0.f);
        acc.w = fmaxf(acc.w + bv.w, 0.f);
    }
    ((float4*)sh[wid])[lane] = acc;
    __syncthreads();

    int d    = tid & 127;
    int half = tid >> 7;
    const float* W   = half ? Wr : Wl;
    const float* bb  = half ? br : bl;
    float*       out = half ? g_xr : g_xl;
    float bd = bb[d];
    float a[8];
    #pragma unroll
    for (int r = 0; r < 8; r++) a[r] = bd;
    #pragma unroll 4
    for (int k = 0; k < DD; k++) {
        float w = W[k * DD + d];
        #pragma unroll
        for (int r = 0; r < 8; r++) a[r] = fmaf(sh[r][k], w, a[r]);
    }
    #pragma unroll
    for (int r = 0; r < 8; r++) {
        int gg = g0 + r;
        if (gg < G) out[(size_t)gg * DD + d] = a[r];
    }
}

// ---------------------------------------------------------------------------
// K5b: L2 prefetch of the first PREF_SLICES W1 slices (96MB). Runs on a
// low-priority stream concurrent with khx, using its spare DRAM bandwidth.
// The data-dependent sink write keeps loads alive; result deterministic.
// ---------------------------------------------------------------------------
__global__ void kpref(const float4* __restrict__ W4, long long n4) {
    long long i = (long long)blockIdx.x * blockDim.x + threadIdx.x;
    long long stride = (long long)gridDim.x * blockDim.x;
    float s = 0.f;
    for (; i < n4; i += stride) {
        float4 v = __ldg(&W4[i]);
        s += v.x + v.y + v.z + v.w;
    }
    if (s == 123.456789f) g_sink = s;
}

// ---------------------------------------------------------------------------
// online-softmax single-edge update
// ---------------------------------------------------------------------------
__device__ __forceinline__ void gat_step(int src, float4 xr4, float4 att4,
                                         const float4* xlv, int lane,
                                         float& m, float& z, float4& acc) {
    float4 xl4 = xlv[(size_t)src * (DD / 4) + lane];
    float tx = xl4.x + xr4.x, ty = xl4.y + xr4.y;
    float tz = xl4.z + xr4.z, tw = xl4.w + xr4.w;
    tx = tx >= 0.f ? tx : 0.2f * tx;
    ty = ty >= 0.f ? ty : 0.2f * ty;
    tz = tz >= 0.f ? tz : 0.2f * tz;
    tw = tw >= 0.f ? tw : 0.2f * tw;
    float p = att4.x * tx + att4.y * ty + att4.z * tz + att4.w * tw;
    #pragma unroll
    for (int o = 16; o; o >>= 1) p += __shfl_xor_sync(0xffffffffu, p, o);
    float mn = fmaxf(m, p);
    float sc = __expf(m - mn);
    float w  = __expf(p - mn);
    z     = z * sc + w;
    acc.x = acc.x * sc + w * xl4.x;
    acc.y = acc.y * sc + w * xl4.y;
    acc.z = acc.z * sc + w * xl4.z;
    acc.w = acc.w * sc + w * xl4.w;
    m = mn;
}

// ---------------------------------------------------------------------------
// K6: FUSED GATv2 + MLP1 slice. 256 threads, one destination node per block.
// Phase A: 8-warp gather, 2 independent online-softmax sets per warp.
// Phase B: stream this block's 64KB W1 slice from GLOBAL (L2-hot for the
// first PREF_SLICES blocks thanks to kpref); small static smem -> many
// resident blocks, so gather latency of some blocks hides under the W1
// stream of others.
// ---------------------------------------------------------------------------
__global__ void kgm(const float* __restrict__ att, const float* __restrict__ bias,
                    const float* __restrict__ W1) {
    int n = blockIdx.x;
    int tid = threadIdx.x, lane = tid & 31, wid = tid >> 5;

    const float4* xlv = (const float4*)g_xl;
    float4 att4 = ((const float4*)att)[lane];
    float4 xr4  = ((const float4*)(g_xr + (size_t)n * DD))[lane];

    int beg = g_off[n], end = g_off[n + 1];
    float  m0 = -INFINITY, z0 = 0.f, m1 = -INFINITY, z1 = 0.f;
    float4 a0 = make_float4(0.f, 0.f, 0.f, 0.f);
    float4 a1 = make_float4(0.f, 0.f, 0.f, 0.f);

    if (wid == 0) gat_step(n, xr4, att4, xlv, lane, m0, z0, a0);  // self loop
    for (int i = beg + wid; i < end; i += 16) {
        int s0 = g_es[i];
        int s1 = (i + 8 < end) ? g_es[i + 8] : -1;
        gat_step(s0, xr4, att4, xlv, lane, m0, z0, a0);
        if (s1 >= 0) gat_step(s1, xr4, att4, xlv, lane, m1, z1, a1);
    }
    {
        float M = fmaxf(m0, m1);
        float s0 = __expf(m0 - M), s1 = __expf(m1 - M);
        z0   = z0 * s0 + z1 * s1;
        a0.x = a0.x * s0 + a1.x * s1;
        a0.y = a0.y * s0 + a1.y * s1;
        a0.z = a0.z * s0 + a1.z * s1;
        a0.w = a0.w * s0 + a1.w * s1;
        m0 = M;
    }

    __shared__ float sm[8], szz[8];
    __shared__ float sacc[8][DD];
    __shared__ float sgat[DD];
    if (lane == 0) { sm[wid] = m0; szz[wid] = z0; }
    sacc[wid][lane * 4 + 0] = a0.x;
    sacc[wid][lane * 4 + 1] = a0.y;
    sacc[wid][lane * 4 + 2] = a0.z;
    sacc[wid][lane * 4 + 3] = a0.w;
    __syncthreads();

    if (tid < DD) {
        int d = tid;
        float M = sm[0];
        #pragma unroll
        for (int w2 = 1; w2 < 8; w2++) M = fmaxf(M, sm[w2]);
        float Z = 0.f, A = 0.f;
        #pragma unroll
        for (int w2 = 0; w2 < 8; w2++) {
            float s = __expf(sm[w2] - M);
            Z += szz[w2] * s;
            A += sacc[w2][d] * s;
        }
        float o = A / Z + bias[d];
        sgat[d] = o >= 0.f ? o : 0.2f * o;
    }
    __syncthreads();

    // phase B: 16 rows per warp, float4 lanes, global loads
    const float4* W4 = (const float4*)(W1 + (size_t)n * DD * DD);
    float4 h = make_float4(0.f, 0.f, 0.f, 0.f);
    #pragma unroll
    for (int r = wid; r < DD; r += 8) {
        float  f = sgat[r];
        float4 w = __ldg(&W4[(size_t)r * 32 + lane]);
        h.x = fmaf(f, w.x, h.x);
        h.y = fmaf(f, w.y, h.y);
        h.z = fmaf(f, w.z, h.z);
        h.w = fmaf(f, w.w, h.w);
    }
    __shared__ float4 sred[8][32];
    sred[wid][lane] = h;
    __syncthreads();
    if (wid == 0) {
        float4 a = sred[0][lane];
        #pragma unroll
        for (int w2 = 1; w2 < 8; w2++) {
            float4 b = sred[w2][lane];
            a.x += b.x; a.y += b.y; a.z += b.z; a.w += b.w;
        }
        float* dst = g_h1p[n & (HR - 1)];
        atomicAdd(&dst[4 * lane + 0], a.x);
        atomicAdd(&dst[4 * lane + 1], a.y);
        atomicAdd(&dst[4 * lane + 2], a.z);
        atomicAdd(&dst[4 * lane + 3], a.w);
    }
}

// ---------------------------------------------------------------------------
// K7: out = relu(sum_replicas h1 + b1) @ W2 + b2
// ---------------------------------------------------------------------------
__global__ void kout(const float* __restrict__ b1, const float* __restrict__ W2,
                     const float* __restrict__ b2, float* __restrict__ out) {
    int d = threadIdx.x;
    float v = b1[d];
    #pragma unroll
    for (int r = 0; r < HR; r++) v += g_h1p[r][d];
    v = fmaxf(v, 0.f);
    float p = v * W2[d];
    #pragma unroll
    for (int o = 16; o; o >>= 1) p += __shfl_xor_sync(0xffffffffu, p, o);
    __shared__ float sp[4];
    if ((d & 31) == 0) sp[d >> 5] = p;
    __syncthreads();
    if (d == 0) out[0] = sp[0] + sp[1] + sp[2] + sp[3] + b2[0];
}

// ---------------------------------------------------------------------------
extern "C" void kernel_launch(void* const* d_in, const int* in_sizes, int n_in,
                              void* d_out, int out_size) {
    const float* x    = (const float*)d_in[0];
    const void*  ei   = d_in[1];
    const float* Win  = (const float*)d_in[2];
    const float* bin  = (const float*)d_in[3];
    const float* Wl   = (const float*)d_in[4];
    const float* bl   = (const float*)d_in[5];
    const float* Wr   = (const float*)d_in[6];
    const float* br   = (const float*)d_in[7];
    const float* att  = (const float*)d_in[8];
    const float* bias = (const float*)d_in[9];
    const float* W1   = (const float*)d_in[10];
    const float* b1   = (const float*)d_in[11];
    const float* W2   = (const float*)d_in[12];
    const float* b2   = (const float*)d_in[13];

    int Dd = in_sizes[8];          // 128
    int G  = in_sizes[3] / Dd;     // 5000
    int IN = in_sizes[0] / G;      // 64
    int E  = in_sizes[1] / 2;      // 240000
    (void)n_in; (void)out_size; (void)Dd;

    static bool inited = false;
    static cudaStream_t sB, sC;
    static cudaEvent_t evF, evE, evP;
    if (!inited) {
        int lo, hi;
        cudaDeviceGetStreamPriorityRange(&lo, &hi);
        cudaStreamCreateWithFlags(&sB, cudaStreamNonBlocking);
        cudaStreamCreateWithPriority(&sC, cudaStreamNonBlocking, lo); // lowest prio
        cudaEventCreateWithFlags(&evF, cudaEventDisableTiming);
        cudaEventCreateWithFlags(&evE, cudaEventDisableTiming);
        cudaEventCreateWithFlags(&evP, cudaEventDisableTiming);
        inited = true;
    }

    int zB  = (G + 255) / 256;
    int eB2 = (E / 2 + 255) / 256;
    int eB4 = (E / 4 + 255) / 256;

    // fork: edge pipeline on sB, W1->L2 prefetch on sC, both concurrent w/ khx
    cudaEventRecord(evF, 0);
    cudaStreamWaitEvent(sB, evF, 0);
    cudaStreamWaitEvent(sC, evF, 0);

    ksetup  <<<zB + 1, 256, 0, sB>>>((const int*)ei, E, G, zB);
    kconv   <<<eB2, 256, 0, sB>>>(ei, E);
    kscan   <<<1, 1024, 0, sB>>>(G);
    kscatter<<<eB4, 256, 0, sB>>>(E);
    cudaEventRecord(evE, sB);

    long long n4 = (long long)PREF_SLICES * DD * DD / 4;   // 96MB in float4
    kpref<<<148, 256, 0, sC>>>((const float4*)W1, n4);
    cudaEventRecord(evP, sC);

    khx<<<(G + 7) / 8, 256>>>(x, Win, bin, Wl, bl, Wr, br, IN, G);

    // join edge pipeline, then fused GAT + W1 stream, then output head
    cudaStreamWaitEvent(0, evE, 0);
    kgm <<<G, 256>>>(att, bias, W1);
    kout<<<1, DD>>>(b1, W2, b2, (float*)d_out);
    cudaStreamWaitEvent(0, evP, 0);   // join prefetch stream (already done)
}